// round 16
// baseline (speedup 1.0000x reference)
#include <cuda_runtime.h>
#include <cuda_bf16.h>
#include <cstdint>
#include <math.h>

#define BATCH 256
#define NHEAD 16
#define HDIM  128
#define HID   2048        // NHEAD * HDIM
#define N3    6144        // 3 * HID

// qkv projections, [B, HID] each (b*HID + h*D + d)
__device__ __align__(16) float g_q[BATCH * HID];
__device__ __align__(16) float g_k[BATCH * HID];
__device__ __align__(16) float g_v[BATCH * HID];

// Split-K partial accumulators for gates GEMM  [B, N3] each
__device__ __align__(16) float g_pa[(size_t)BATCH * N3];
__device__ __align__(16) float g_pb[(size_t)BATCH * N3];

// Split-precision scratch (bf16 hi/lo)
__device__ __align__(16) __nv_bfloat16 s_xh[BATCH * HID];
__device__ __align__(16) __nv_bfloat16 s_xl[BATCH * HID];
__device__ __align__(16) __nv_bfloat16 s_wh[(size_t)N3 * HID];   // W_i^T [6144,2048]
__device__ __align__(16) __nv_bfloat16 s_wl[(size_t)N3 * HID];
__device__ __align__(16) __nv_bfloat16 s_wqh[NHEAD * 384 * HDIM]; // W_qkv^T [h][384][128]
__device__ __align__(16) __nv_bfloat16 s_wql[NHEAD * 384 * HDIM];

// ---------------------------------------------------------------------------
// PTX helpers
// ---------------------------------------------------------------------------
__device__ __forceinline__ void cp_async16(uint32_t dst, const void* src) {
    asm volatile("cp.async.cg.shared.global [%0], [%1], 16;"
                 :: "r"(dst), "l"(src));
}
__device__ __forceinline__ void cp_commit() {
    asm volatile("cp.async.commit_group;");
}

__device__ __forceinline__ void ldm_x4(uint32_t* r, uint32_t addr) {
    asm volatile("ldmatrix.sync.aligned.m8n8.x4.shared.b16 {%0,%1,%2,%3}, [%4];"
                 : "=r"(r[0]), "=r"(r[1]), "=r"(r[2]), "=r"(r[3]) : "r"(addr));
}

__device__ __forceinline__ void mma16816(float* c, const uint32_t* a, const uint32_t* b) {
    asm volatile(
        "mma.sync.aligned.m16n8k16.row.col.f32.bf16.bf16.f32 "
        "{%0,%1,%2,%3}, {%4,%5,%6,%7}, {%8,%9}, {%0,%1,%2,%3};"
        : "+f"(c[0]), "+f"(c[1]), "+f"(c[2]), "+f"(c[3])
        : "r"(a[0]), "r"(a[1]), "r"(a[2]), "r"(a[3]), "r"(b[0]), "r"(b[1]));
}

// Pack two floats into bf16x2 split (hi pair + lo pair)
__device__ __forceinline__ void split2(float v0, float v1, uint32_t& H, uint32_t& L) {
    __nv_bfloat16 h0 = __float2bfloat16(v0);
    __nv_bfloat16 h1 = __float2bfloat16(v1);
    __nv_bfloat162 hh; hh.x = h0; hh.y = h1;
    __nv_bfloat162 ll;
    ll.x = __float2bfloat16(v0 - __bfloat162float(h0));
    ll.y = __float2bfloat16(v1 - __bfloat162float(h1));
    H = *(uint32_t*)&hh;
    L = *(uint32_t*)&ll;
}

// ===========================================================================
// Unified prep kernel (R14-validated):
//   blocks [0, 3072)    : splitT_w, 64x64 tiles, float4 loads, bf16x4 stores
//   blocks [3072, 3840) : splitT_wq (32x32 tiles)
//   blocks [3840, 4352) : split_x (float4 in)
// ===========================================================================
__global__ __launch_bounds__(256) void prep_kernel(
    const float* __restrict__ W, const float* __restrict__ Wq,
    const float* __restrict__ x)
{
    __shared__ float tile[64][65];
    const int bid = blockIdx.x;
    const int t = threadIdx.x;

    if (bid < 3072) {
        // splitT_w: W_i [2048,6144] -> wh/wl [6144,2048], 64x64 tile
        const int n0 = (bid % 96) * 64;
        const int k0 = (bid / 96) * 64;
        const int nc4 = (t & 15) * 4;
        const int kb = t >> 4;             // 0..15
        #pragma unroll
        for (int j = 0; j < 4; j++) {
            const int kr = kb + j * 16;
            float4 v = *(const float4*)(W + (size_t)(k0 + kr) * N3 + n0 + nc4);
            tile[kr][nc4 + 0] = v.x;
            tile[kr][nc4 + 1] = v.y;
            tile[kr][nc4 + 2] = v.z;
            tile[kr][nc4 + 3] = v.w;
        }
        __syncthreads();
        const int kq = t & 15;             // k quad (4 k's)
        const int nb = t >> 4;             // 0..15
        #pragma unroll
        for (int j = 0; j < 4; j++) {
            const int n = nb + j * 16;
            float v0 = tile[kq * 4 + 0][n];
            float v1 = tile[kq * 4 + 1][n];
            float v2 = tile[kq * 4 + 2][n];
            float v3 = tile[kq * 4 + 3][n];
            uint2 H, L;
            split2(v0, v1, H.x, L.x);
            split2(v2, v3, H.y, L.y);
            size_t o = (size_t)(n0 + n) * HID + k0 + kq * 4;
            *(uint2*)(s_wh + o) = H;
            *(uint2*)(s_wl + o) = L;
        }
    } else if (bid < 3840) {
        // splitT_wq: W_qkv [h][128][384] -> [h][384][128], 32x32 tile
        const int q = bid - 3072;
        const int n0 = (q % 12) * 32;
        const int k0 = ((q / 12) & 3) * 32;
        const int h  = q / 48;
        const int tx = t & 31;
        const int ty = t >> 5;
        #pragma unroll
        for (int j = 0; j < 4; j++)
            tile[ty + j * 8][tx] = Wq[((size_t)h * HDIM + k0 + ty + j * 8) * 384 + n0 + tx];
        __syncthreads();
        const int kq = t & 7;              // k quad 0..7
        const int nb = t >> 3;             // 0..31
        {
            const int n = nb;
            float v0 = tile[kq * 4 + 0][n];
            float v1 = tile[kq * 4 + 1][n];
            float v2 = tile[kq * 4 + 2][n];
            float v3 = tile[kq * 4 + 3][n];
            uint2 H, L;
            split2(v0, v1, H.x, L.x);
            split2(v2, v3, H.y, L.y);
            size_t o = ((size_t)h * 384 + n0 + n) * HDIM + k0 + kq * 4;
            *(uint2*)(s_wqh + o) = H;
            *(uint2*)(s_wql + o) = L;
        }
    } else {
        // split_x: float4 in, bf16x4 out per array
        const int i4 = (bid - 3840) * 256 + t;     // float4 index
        float4 v = ((const float4*)x)[i4];
        uint2 H, L;
        split2(v.x, v.y, H.x, L.x);
        split2(v.z, v.w, H.y, L.y);
        ((uint2*)s_xh)[i4] = H;
        ((uint2*)s_xl)[i4] = L;
    }
}

// ===========================================================================
// Unified MMA kernel: blocks 0..255 = gates (merged-term, split-K=2),
// blocks 256..351 = qkv. Both validated mainloops unchanged (R11/R12).
// ===========================================================================
#define XH_OFF 0
#define XL_OFF 16384
#define WH_OFF 32768
#define WL_OFF 45056
#define CH_STRIDE 57344           // 56KB per chunk buffer
#define G_DSMEM (2 * CH_STRIDE)   // 114688
#define G_NCHUNK 16               // per split-K half

#define SST 72                        // padded rows for qkv path (144B)
#define Q_STAGE (2 * 128 * SST * 2)   // 36864
#define Q_NSTAGES 6

__device__ __forceinline__ uint32_t swz(int row, int cu) {
    return (uint32_t)(row * 128 + ((cu ^ (row & 7)) << 4));
}

__device__ void gates_body(int bid, __nv_bfloat16* smem)
{
    const int tid = threadIdx.x;
    const int lane = tid & 31;
    const int wid = tid >> 5;
    const int warp_m = (wid & 3) * 32;
    const int warp_n = (wid >> 2) * 48;
    const int n0 = (bid & 63) * 96;
    const int m0 = ((bid >> 6) & 1) * 128;
    const int bz = bid >> 7;
    const int zbase = bz * G_NCHUNK;

    const int r_s = tid >> 3;
    const int seg = tid & 7;

    const uint32_t sbase = (uint32_t)__cvta_generic_to_shared(smem);

    float c[2][6][4];
    #pragma unroll
    for (int i = 0; i < 2; i++)
        #pragma unroll
        for (int j = 0; j < 6; j++)
            #pragma unroll
            for (int q = 0; q < 4; q++) c[i][j][q] = 0.0f;

    auto load_chunk = [&](int cc) {
        const int k0 = (zbase + cc) << 6;
        const uint32_t buf = sbase + (uint32_t)(cc & 1) * CH_STRIDE;
        #pragma unroll
        for (int h = 0; h < 4; h++) {
            const int row = r_s + h * 32;
            const uint32_t sw = swz(row, seg);
            cp_async16(buf + XH_OFF + sw,
                       s_xh + (size_t)(m0 + row) * HID + k0 + seg * 8);
            cp_async16(buf + XL_OFF + sw,
                       s_xl + (size_t)(m0 + row) * HID + k0 + seg * 8);
        }
        #pragma unroll
        for (int h = 0; h < 3; h++) {
            const int row = r_s + h * 32;
            const uint32_t sw = swz(row, seg);
            cp_async16(buf + WH_OFF + sw,
                       s_wh + (size_t)(n0 + row) * HID + k0 + seg * 8);
            cp_async16(buf + WL_OFF + sw,
                       s_wl + (size_t)(n0 + row) * HID + k0 + seg * 8);
        }
        cp_commit();
    };

    load_chunk(0);

    for (int cc = 0; cc < G_NCHUNK; ++cc) {
        asm volatile("cp.async.wait_group 0;");
        __syncthreads();
        if (cc + 1 < G_NCHUNK) load_chunk(cc + 1);

        const uint32_t buf = sbase + (uint32_t)(cc & 1) * CH_STRIDE;

        #pragma unroll
        for (int ki = 0; ki < 4; ki++) {
            const int cub = ki * 2;

            uint32_t axh[2][4], axl[2][4];
            #pragma unroll
            for (int slab = 0; slab < 2; slab++) {
                const int row = warp_m + slab * 16 + (lane & 15);
                const uint32_t off = swz(row, cub + (lane >> 4));
                ldm_x4(axh[slab], buf + XH_OFF + off);
                ldm_x4(axl[slab], buf + XL_OFF + off);
            }

            uint32_t bwh[6][2], bwl[6][2];
            const int g = lane >> 3;
            #pragma unroll
            for (int nb = 0; nb < 3; nb++) {
                const int nrow = warp_n + nb * 16 + ((g >> 1) << 3) + (lane & 7);
                const uint32_t off = swz(nrow, cub + (g & 1));
                uint32_t rr[4];
                ldm_x4(rr, buf + WH_OFF + off);
                bwh[nb * 2 + 0][0] = rr[0]; bwh[nb * 2 + 0][1] = rr[1];
                bwh[nb * 2 + 1][0] = rr[2]; bwh[nb * 2 + 1][1] = rr[3];
                uint32_t r2[4];
                ldm_x4(r2, buf + WL_OFF + off);
                bwl[nb * 2 + 0][0] = r2[0]; bwl[nb * 2 + 0][1] = r2[1];
                bwl[nb * 2 + 1][0] = r2[2]; bwl[nb * 2 + 1][1] = r2[3];
            }

            #pragma unroll
            for (int slab = 0; slab < 2; slab++)
                #pragma unroll
                for (int j = 0; j < 6; j++) {
                    mma16816(c[slab][j], axh[slab], bwh[j]);
                    mma16816(c[slab][j], axl[slab], bwh[j]);
                    mma16816(c[slab][j], axh[slab], bwl[j]);
                }
        }
    }

    float* pout = (bz == 0) ? g_pa : g_pb;
    #pragma unroll
    for (int slab = 0; slab < 2; slab++) {
        const int mrow = m0 + warp_m + slab * 16 + (lane >> 2);
        #pragma unroll
        for (int j = 0; j < 6; j++) {
            const int col = n0 + warp_n + j * 8 + ((lane & 3) << 1);
            *(float2*)(pout + (size_t)mrow * N3 + col) =
                make_float2(c[slab][j][0], c[slab][j][1]);
            *(float2*)(pout + (size_t)(mrow + 8) * N3 + col) =
                make_float2(c[slab][j][2], c[slab][j][3]);
        }
    }
}

__device__ void qkv_body(int qb, __nv_bfloat16* smem, const float* __restrict__ bq)
{
    const int tid = threadIdx.x;
    const int lane = tid & 31;
    const int wid = tid >> 5;
    const int warp_m = (wid & 3) * 32;
    const int warp_n = (wid >> 2) * 64;
    const int n0 = (qb % 3) * 128;
    const int m0 = ((qb / 3) & 1) * 128;
    const int head = qb / 6;

    const int r_s = tid >> 3;
    const int seg = tid & 7;

    const uint32_t sbase = (uint32_t)__cvta_generic_to_shared(smem);

    float c[2][8][4];
    #pragma unroll
    for (int i = 0; i < 2; i++)
        #pragma unroll
        for (int j = 0; j < 8; j++)
            #pragma unroll
            for (int q = 0; q < 4; q++) c[i][j][q] = 0.0f;

    auto load_stage = [&](int s) {
        const int term = s >> 1;
        const int k0 = (s & 1) << 6;
        const __nv_bfloat16* Ap = (term == 1) ? s_xl : s_xh;
        const __nv_bfloat16* Bp = (term == 2) ? s_wql : s_wqh;
        const uint32_t buf = sbase + (uint32_t)(s % 3) * Q_STAGE;
        #pragma unroll
        for (int h = 0; h < 4; h++) {
            const int row = r_s + h * 32;
            const uint32_t doff = (uint32_t)(row * 144 + seg * 16);
            cp_async16(buf + doff,
                       Ap + (size_t)(m0 + row) * HID + head * HDIM + k0 + seg * 8);
            cp_async16(buf + (uint32_t)(128 * 144) + doff,
                       Bp + ((size_t)head * 384 + n0 + row) * HDIM + k0 + seg * 8);
        }
    };

    auto load_frags = [&](uint32_t Ab, uint32_t Bb, int kk,
                          uint32_t af[2][4], uint32_t bf[8][2]) {
        #pragma unroll
        for (int slab = 0; slab < 2; slab++) {
            const int row = warp_m + slab * 16 + (lane & 15);
            const int col = kk + ((lane >> 4) << 3);
            ldm_x4(af[slab], Ab + (uint32_t)(row * SST + col) * 2);
        }
        const int g = lane >> 3;
        #pragma unroll
        for (int nb = 0; nb < 4; nb++) {
            const int nrow = warp_n + nb * 16 + ((g >> 1) << 3) + (lane & 7);
            const int col = kk + ((g & 1) << 3);
            uint32_t rr[4];
            ldm_x4(rr, Bb + (uint32_t)(nrow * SST + col) * 2);
            bf[nb * 2 + 0][0] = rr[0]; bf[nb * 2 + 0][1] = rr[1];
            bf[nb * 2 + 1][0] = rr[2]; bf[nb * 2 + 1][1] = rr[3];
        }
    };

    load_stage(0); cp_commit();
    load_stage(1); cp_commit();

    uint32_t af[2][2][4];
    uint32_t bf[2][8][2];

    for (int s = 0; s < Q_NSTAGES; ++s) {
        asm volatile("cp.async.wait_group 1;");
        __syncthreads();
        if (s + 2 < Q_NSTAGES) load_stage(s + 2);
        cp_commit();

        const uint32_t Ab = sbase + (uint32_t)(s % 3) * Q_STAGE;
        const uint32_t Bb = Ab + (uint32_t)(128 * 144);

        load_frags(Ab, Bb, 0, af[0], bf[0]);
        #pragma unroll
        for (int ki = 0; ki < 4; ki++) {
            const int cur = ki & 1;
            if (ki < 3)
                load_frags(Ab, Bb, (ki + 1) * 16, af[cur ^ 1], bf[cur ^ 1]);
            #pragma unroll
            for (int slab = 0; slab < 2; slab++)
                #pragma unroll
                for (int j = 0; j < 8; j++)
                    mma16816(c[slab][j], af[cur][slab], bf[cur][j]);
        }
    }

    const float kscale = 0.08838834764831845f;   // 1/sqrt(128)

    #pragma unroll
    for (int slab = 0; slab < 2; slab++) {
        const int mrow = m0 + warp_m + slab * 16 + (lane >> 2);
        #pragma unroll
        for (int j = 0; j < 8; j++) {
            const int ncol = n0 + warp_n + j * 8 + ((lane & 3) << 1);
            const int cls = ncol >> 7;          // 0:q 1:k 2:v
            float* outp = (cls == 0) ? g_q : ((cls == 1) ? g_k : g_v);
            const int colb = ncol & 127;
            const float b0 = bq[head * 384 + ncol];
            const float b1 = bq[head * 384 + ncol + 1];
            float t0 = c[slab][j][0] + b0, t1 = c[slab][j][1] + b1;
            float t2 = c[slab][j][2] + b0, t3 = c[slab][j][3] + b1;
            if (cls == 1) { t0 *= kscale; t1 *= kscale; t2 *= kscale; t3 *= kscale; }
            *(float2*)(outp + (size_t)mrow * HID + head * HDIM + colb) =
                make_float2(t0, t1);
            *(float2*)(outp + (size_t)(mrow + 8) * HID + head * HDIM + colb) =
                make_float2(t2, t3);
        }
    }
}

__global__ __launch_bounds__(256, 2) void mma_kernel(const float* __restrict__ bq)
{
    extern __shared__ __nv_bfloat16 smem[];
    if (blockIdx.x < 256) gates_body(blockIdx.x, smem);
    else                  qkv_body(blockIdx.x - 256, smem, bq);
}

// ---------------------------------------------------------------------------
// Fused state update + gates epilogue (R13-validated version: default-policy
// loads/stores, unroll 4 — L2 residency across graph replays is load-bearing).
// ---------------------------------------------------------------------------
__global__ __launch_bounds__(128) void state_kernel(
    const float* __restrict__ Cin, const float* __restrict__ nin,
    const float* __restrict__ bias,
    float* __restrict__ out_h, float* __restrict__ out_C,
    float* __restrict__ out_n)
{
    __shared__ float q_s[128], k_s[128];
    __shared__ float f_s[128], a_s[128], o_s[128];
    __shared__ float red[4];
    __shared__ float s_inv;

    const int t = threadIdx.x;
    const int w = t >> 5;
    const int lane = t & 31;
    const int vo = blockIdx.x * HDIM;

    const size_t rowb = (size_t)(blockIdx.x >> 4) * N3;
    const int hid = ((blockIdx.x & 15) << 7) + t;

    float ti = g_pa[rowb + hid] + g_pb[rowb + hid] + bias[hid];
    float tf = g_pa[rowb + 2048 + hid] + g_pb[rowb + 2048 + hid] + bias[2048 + hid];
    float to = g_pa[rowb + 4096 + hid] + g_pb[rowb + 4096 + hid] + bias[4096 + hid];
    float iv = expf(ti);
    float fv = expf(tf);
    float ov = 1.0f / (1.0f + expf(-to));

    float qv = g_q[vo + t], kv = g_k[vo + t], vv = g_v[vo + t];
    float nv = nin[vo + t];

    float nn = fv * nv + iv * kv;
    out_n[vo + t] = nn;

    q_s[t] = qv; k_s[t] = kv;
    f_s[t] = fv; a_s[t] = iv * vv; o_s[t] = ov;

    float p = nn * qv;
    #pragma unroll
    for (int off = 16; off; off >>= 1) p += __shfl_xor_sync(0xffffffffu, p, off);
    if (lane == 0) red[w] = p;
    __syncthreads();
    if (t == 0) {
        float dot = red[0] + red[1] + red[2] + red[3];
        s_inv = 1.0f / fmaxf(fabsf(dot), 1.0f);
    }
    __syncthreads();
    const float inv = s_inv;

    const float4 q4 = ((const float4*)q_s)[lane];
    const float4 k4 = ((const float4*)k_s)[lane];
    const float4* C4 = (const float4*)(Cin + (size_t)blockIdx.x * HDIM * HDIM);
    float4* O4 = (float4*)(out_C + (size_t)blockIdx.x * HDIM * HDIM);

    #pragma unroll 4
    for (int r = 0; r < 32; r++) {
        const int d = (w << 5) + r;
        float4 cc = C4[d * 32 + lane];
        float part = cc.x * q4.x + cc.y * q4.y + cc.z * q4.z + cc.w * q4.w;
        const float fd = f_s[d], ad = a_s[d];
        float4 cn;
        cn.x = fd * cc.x + ad * k4.x;
        cn.y = fd * cc.y + ad * k4.y;
        cn.z = fd * cc.z + ad * k4.z;
        cn.w = fd * cc.w + ad * k4.w;
        O4[d * 32 + lane] = cn;
        #pragma unroll
        for (int off = 16; off; off >>= 1)
            part += __shfl_xor_sync(0xffffffffu, part, off);
        if (lane == 0) out_h[vo + d] = o_s[d] * part * inv;
    }
}

// ---------------------------------------------------------------------------
// Launch
// ---------------------------------------------------------------------------
extern "C" void kernel_launch(void* const* d_in, const int* in_sizes, int n_in,
                              void* d_out, int out_size)
{
    const float* x     = (const float*)d_in[0];
    const float* C     = (const float*)d_in[2];
    const float* n     = (const float*)d_in[3];
    const float* W_i   = (const float*)d_in[4];
    const float* b_i   = (const float*)d_in[5];
    const float* W_qkv = (const float*)d_in[6];
    const float* b_qkv = (const float*)d_in[7];

    float* out   = (float*)d_out;
    float* out_h = out;
    float* out_C = out + (size_t)BATCH * HID;
    float* out_n = out_C + (size_t)BATCH * NHEAD * HDIM * HDIM;

    cudaFuncSetAttribute(mma_kernel,
                         cudaFuncAttributeMaxDynamicSharedMemorySize, G_DSMEM);

    prep_kernel<<<4352, 256>>>(W_i, W_qkv, x);
    mma_kernel<<<352, 256, G_DSMEM>>>(b_qkv);
    state_kernel<<<BATCH * NHEAD, 128>>>(C, n, b_i, out_h, out_C, out_n);
}